// round 2
// baseline (speedup 1.0000x reference)
#include <cuda_runtime.h>

#define WIDTH    512
#define HEIGHT   512
#define TH       64
#define STRIPS   (HEIGHT / TH)      // 8
#define CHANNELS 96                 // 32 * 3
#define NBLK     (STRIPS * CHANNELS) // 768

#define C1v 1.0e-4f
#define C2v 9.0e-4f

// Gaussian(sigma=1.5, k=11) normalized weights. Declared as a function-local
// constexpr array (device-usable without --expt-relaxed-constexpr); all
// indices are compile-time so values fold into FFMA immediates (rt_SMSP=1).
#define DECL_KW \
    constexpr float KW[11] = { \
        0.00102838f, 0.00759876f, 0.03600078f, 0.10936081f, 0.21300554f, \
        0.26601173f, \
        0.21300554f, 0.10936081f, 0.03600078f, 0.00759876f, 0.00102838f }

__device__ float g_partial[NBLK];

__global__ void __launch_bounds__(512, 1)
ssim_main(const float* __restrict__ pred, const float* __restrict__ targ) {
    DECL_KW;
    // Vertical-conv results staged per row: float4(vp,vt,vpp,vtt) + float(vpt).
    // Index x+5; slots [0..4] and [517..521] are permanent zero pads (x halo).
    __shared__ float4 s4[2][WIDTH + 12];
    __shared__ float  s1[2][WIDTH + 12];
    __shared__ float  wsum[16];

    const int x  = threadIdx.x;          // column, 0..511
    const int y0 = blockIdx.x * TH;      // strip start row
    const int ch = blockIdx.y;           // image-channel 0..95
    const float* __restrict__ P = pred + (size_t)ch * (WIDTH * HEIGHT);
    const float* __restrict__ T = targ + (size_t)ch * (WIDTH * HEIGHT);

    // zero the x-halo pads once (read every iter, never rewritten)
    if (x < 5) {
        s4[0][x] = make_float4(0.f, 0.f, 0.f, 0.f);
        s4[1][x] = make_float4(0.f, 0.f, 0.f, 0.f);
        s1[0][x] = 0.f; s1[1][x] = 0.f;
    }
    if (x >= WIDTH - 5) {
        s4[0][x + 10] = make_float4(0.f, 0.f, 0.f, 0.f);
        s4[1][x + 10] = make_float4(0.f, 0.f, 0.f, 0.f);
        s1[0][x + 10] = 0.f; s1[1][x + 10] = 0.f;
    }

    // Register ring buffers over 11 rows; all indices compile-time constant.
    float rP[11], rT[11], rPP[11], rTT[11], rPT[11];

    // Prologue: rows y0-5 .. y0+5  (row counter k = 0..10, slot = k)
    #pragma unroll
    for (int k = 0; k < 11; k++) {
        const int r = y0 - 5 + k;
        float p = 0.f, t = 0.f;
        if ((unsigned)r < (unsigned)HEIGHT) {
            p = P[r * WIDTH + x];
            t = T[r * WIDTH + x];
        }
        rP[k] = p; rT[k] = t;
        rPP[k] = p * p; rTT[k] = t * t; rPT[k] = p * t;
    }

    float acc = 0.f;

    // Output row j (absolute y0+j) uses ring slots (j+i)%11, i=0..10.
    // Chunked 11-unroll keeps slot = (u+i)%11 compile-time (jc % 11 == 0).
    #pragma unroll 1
    for (int jc = 0; jc < TH; jc += 11) {
        #pragma unroll
        for (int u = 0; u < 11; u++) {
            const int j = jc + u;
            if (j >= TH) break;  // uniform across block

            // --- vertical conv (FFMA-imm) ---
            float vp = 0.f, vt = 0.f, vpp = 0.f, vtt = 0.f, vpt = 0.f;
            #pragma unroll
            for (int i = 0; i < 11; i++) {
                const int s = (u + i) % 11;
                vp  = fmaf(rP[s],  KW[i], vp);
                vt  = fmaf(rT[s],  KW[i], vt);
                vpp = fmaf(rPP[s], KW[i], vpp);
                vtt = fmaf(rTT[s], KW[i], vtt);
                vpt = fmaf(rPT[s], KW[i], vpt);
            }

            // --- prefetch next input row (abs row y0+j+6) into slot u ---
            if (j < TH - 1) {
                const int r = y0 + j + 6;
                float p = 0.f, t = 0.f;
                if ((unsigned)r < (unsigned)HEIGHT) {
                    p = P[r * WIDTH + x];
                    t = T[r * WIDTH + x];
                }
                rP[u] = p; rT[u] = t;
                rPP[u] = p * p; rTT[u] = t * t; rPT[u] = p * t;
            }

            // --- stage vertical results (double-buffered) ---
            const int buf = j & 1;
            s4[buf][x + 5] = make_float4(vp, vt, vpp, vtt);
            s1[buf][x + 5] = vpt;
            __syncthreads();

            // --- horizontal conv (LDS.128 + LDS.32, FFMA-imm) ---
            float hp = 0.f, ht = 0.f, hpp = 0.f, htt = 0.f, hpt = 0.f;
            #pragma unroll
            for (int i = 0; i < 11; i++) {
                const float4 a = s4[buf][x + i];
                const float  b = s1[buf][x + i];
                hp  = fmaf(a.x, KW[i], hp);
                ht  = fmaf(a.y, KW[i], ht);
                hpp = fmaf(a.z, KW[i], hpp);
                htt = fmaf(a.w, KW[i], htt);
                hpt = fmaf(b,   KW[i], hpt);
            }

            // --- SSIM ---
            const float mup2 = hp * hp;
            const float mut2 = ht * ht;
            const float mupt = hp * ht;
            const float sp   = hpp - mup2;
            const float st   = htt - mut2;
            const float spt  = hpt - mupt;
            const float num  = fmaf(2.f, mupt, C1v) * fmaf(2.f, spt, C2v);
            const float den  = (mup2 + mut2 + C1v) * (sp + st + C2v);
            acc += __fdividef(num, den);
        }
    }

    // --- deterministic block reduction ---
    const int lane = x & 31;
    const int wid  = x >> 5;
    #pragma unroll
    for (int o = 16; o > 0; o >>= 1)
        acc += __shfl_down_sync(0xffffffffu, acc, o);
    if (lane == 0) wsum[wid] = acc;
    __syncthreads();
    if (wid == 0) {
        float v = (lane < 16) ? wsum[lane] : 0.f;
        #pragma unroll
        for (int o = 8; o > 0; o >>= 1)
            v += __shfl_down_sync(0xffffffffu, v, o);
        if (lane == 0)
            g_partial[blockIdx.y * STRIPS + blockIdx.x] = v;
    }
}

// Fixed-order fp64 final reduction (deterministic; fp32 cannot hold a ~25M sum).
__global__ void ssim_reduce(float* __restrict__ out) {
    __shared__ double sh[256];
    const int t = threadIdx.x;
    double s = 0.0;
    for (int i = t; i < NBLK; i += 256)
        s += (double)g_partial[i];
    sh[t] = s;
    __syncthreads();
    #pragma unroll 1
    for (int o = 128; o > 0; o >>= 1) {
        if (t < o) sh[t] += sh[t + o];
        __syncthreads();
    }
    if (t == 0)
        out[0] = (float)(1.0 - sh[0] / 25165824.0);  // 32*3*512*512
}

extern "C" void kernel_launch(void* const* d_in, const int* in_sizes, int n_in,
                              void* d_out, int out_size) {
    const float* pred = (const float*)d_in[0];
    const float* targ = (const float*)d_in[1];
    ssim_main<<<dim3(STRIPS, CHANNELS), 512>>>(pred, targ);
    ssim_reduce<<<1, 256>>>((float*)d_out);
}

// round 3
// speedup vs baseline: 2.0210x; 2.0210x over previous
#include <cuda_runtime.h>

#define WIDTH    512
#define HEIGHT   512
#define TH       128
#define TH_IN    (TH + 10)           // 138 input rows per strip
#define STRIPS   (HEIGHT / TH)       // 4
#define CHANNELS 96                  // 32 * 3
#define NBLK     (STRIPS * CHANNELS) // 384

#define C1v 1.0e-4f
#define C2v 9.0e-4f

// Gaussian(sigma=1.5, k=11) weights; function-local constexpr with
// compile-time indices -> values fold into FFMA immediates (rt_SMSP=1).
#define DECL_KW \
    constexpr float KW[11] = { \
        0.00102838f, 0.00759876f, 0.03600078f, 0.10936081f, 0.21300554f, \
        0.26601173f, \
        0.21300554f, 0.10936081f, 0.03600078f, 0.00759876f, 0.00102838f }

__device__ float g_partial[NBLK];

__global__ void __launch_bounds__(512, 1)
ssim_main(const float* __restrict__ pred, const float* __restrict__ targ) {
    DECL_KW;
    // Raw (e,d) rows staged as float2, double-buffered, with permanent
    // zero x-halo pads at [0..4] and [517..521]. 8 B/pixel staged,
    // 88 B/pixel read by the horizontal pass (was 220 B/pixel).
    __shared__ float2 sED[2][WIDTH + 12];
    __shared__ float  wsum[16];

    const int x  = threadIdx.x;          // column 0..511
    const int y0 = blockIdx.x * TH;      // strip start output row
    const int ch = blockIdx.y;           // image-channel 0..95
    const float* __restrict__ P = pred + (size_t)ch * (WIDTH * HEIGHT);
    const float* __restrict__ T = targ + (size_t)ch * (WIDTH * HEIGHT);

    if (x < 5) {
        sED[0][x] = make_float2(0.f, 0.f);
        sED[1][x] = make_float2(0.f, 0.f);
    }
    if (x >= WIDTH - 5) {
        sED[0][x + 10] = make_float2(0.f, 0.f);
        sED[1][x + 10] = make_float2(0.f, 0.f);
    }

    // Vertical ring over 11 horizontal-conv result rows (4 quantities).
    float rHE[11], rHD[11], rHE2[11], rHD2[11];
    float acc = 0.f;

    // Prefetch input row k=0 (abs row y0-5).
    float pN = 0.f, tN = 0.f;
    {
        const int r = y0 - 5;
        if ((unsigned)r < (unsigned)HEIGHT) {
            pN = P[r * WIDTH + x];
            tN = T[r * WIDTH + x];
        }
    }

    // Input-row counter k = 0..TH_IN-1; ring slot = k % 11 = u (kc % 11 == 0).
    #pragma unroll 1
    for (int kc = 0; kc < TH_IN; kc += 11) {
        #pragma unroll
        for (int u = 0; u < 11; u++) {
            const int k = kc + u;
            if (k >= TH_IN) break;  // uniform across block

            const float p = pN, t = tN;
            // prefetch next input row (abs y0-4+k)
            if (k + 1 < TH_IN) {
                const int r = y0 - 4 + k;
                if ((unsigned)r < (unsigned)HEIGHT) {
                    pN = P[r * WIDTH + x];
                    tN = T[r * WIDTH + x];
                } else { pN = 0.f; tN = 0.f; }
            }

            // stage (e, d) for this row
            const float e = p + t, d = p - t;
            const int buf = k & 1;
            sED[buf][x + 5] = make_float2(e, d);
            __syncthreads();

            // horizontal conv: he, hd, he2, hd2  (squares computed per-tap)
            float he = 0.f, hd = 0.f, he2 = 0.f, hd2 = 0.f;
            #pragma unroll
            for (int i = 0; i < 11; i++) {
                const float2 v = sED[buf][x + i];
                he  = fmaf(v.x,       KW[i], he);
                hd  = fmaf(v.y,       KW[i], hd);
                he2 = fmaf(v.x * v.x, KW[i], he2);
                hd2 = fmaf(v.y * v.y, KW[i], hd2);
            }
            rHE[u] = he; rHD[u] = hd; rHE2[u] = he2; rHD2[u] = hd2;

            // vertical conv + SSIM once ring is full (output row k-10)
            if (k >= 10) {
                float me = 0.f, md = 0.f, ce2 = 0.f, cd2 = 0.f;
                #pragma unroll
                for (int i = 0; i < 11; i++) {
                    const int s = (u + 1 + i) % 11;  // row k-10+i
                    me  = fmaf(rHE[s],  KW[i], me);
                    md  = fmaf(rHD[s],  KW[i], md);
                    ce2 = fmaf(rHE2[s], KW[i], ce2);
                    cd2 = fmaf(rHD2[s], KW[i], cd2);
                }
                // SSIM from e/d moments:
                //  mu_p*mu_t        = (me^2 - md^2)/4
                //  mu_p^2 + mu_t^2  = (me^2 + md^2)/2
                //  conv(pt)         = (ce2 - cd2)/4
                //  conv(pp)+conv(tt)= (ce2 + cd2)/2
                const float A  = me * me;
                const float B  = md * md;
                const float t1 = A - B;
                const float t2 = A + B;
                const float n1 = fmaf(0.5f, t1, C1v);
                const float d1 = fmaf(0.5f, t2, C1v);
                const float n2 = fmaf(0.5f, (ce2 - cd2) - t1, C2v);
                const float d2 = fmaf(0.5f, (ce2 + cd2) - t2, C2v);
                acc += __fdividef(n1 * n2, d1 * d2);
            }
        }
    }

    // deterministic block reduction
    const int lane = x & 31;
    const int wid  = x >> 5;
    #pragma unroll
    for (int o = 16; o > 0; o >>= 1)
        acc += __shfl_down_sync(0xffffffffu, acc, o);
    if (lane == 0) wsum[wid] = acc;
    __syncthreads();
    if (wid == 0) {
        float v = (lane < 16) ? wsum[lane] : 0.f;
        #pragma unroll
        for (int o = 8; o > 0; o >>= 1)
            v += __shfl_down_sync(0xffffffffu, v, o);
        if (lane == 0)
            g_partial[blockIdx.y * STRIPS + blockIdx.x] = v;
    }
}

// Fixed-order fp64 final reduction (deterministic; fp32 cannot hold a ~25M sum).
__global__ void ssim_reduce(float* __restrict__ out) {
    __shared__ double sh[256];
    const int t = threadIdx.x;
    double s = 0.0;
    for (int i = t; i < NBLK; i += 256)
        s += (double)g_partial[i];
    sh[t] = s;
    __syncthreads();
    #pragma unroll 1
    for (int o = 128; o > 0; o >>= 1) {
        if (t < o) sh[t] += sh[t + o];
        __syncthreads();
    }
    if (t == 0)
        out[0] = (float)(1.0 - sh[0] / 25165824.0);  // 32*3*512*512
}

extern "C" void kernel_launch(void* const* d_in, const int* in_sizes, int n_in,
                              void* d_out, int out_size) {
    const float* pred = (const float*)d_in[0];
    const float* targ = (const float*)d_in[1];
    ssim_main<<<dim3(STRIPS, CHANNELS), 512>>>(pred, targ);
    ssim_reduce<<<1, 256>>>((float*)d_out);
}

// round 4
// speedup vs baseline: 2.0248x; 1.0019x over previous
#include <cuda_runtime.h>

#define WIDTH    512
#define HEIGHT   512
#define TH       128
#define TH_IN    (TH + 10)           // 138 input rows per strip
#define STRIPS   (HEIGHT / TH)       // 4
#define CHANNELS 96                  // 32 * 3
#define NBLK     (STRIPS * CHANNELS) // 384

#define C1v 1.0e-4f
#define C2v 9.0e-4f

typedef unsigned long long u64;

// Gaussian(sigma=1.5, k=11) weights; compile-time indices only.
#define DECL_KW \
    constexpr float KW[11] = { \
        0.00102838f, 0.00759876f, 0.03600078f, 0.10936081f, 0.21300554f, \
        0.26601173f, \
        0.21300554f, 0.10936081f, 0.03600078f, 0.00759876f, 0.00102838f }

// ---- packed f32x2 helpers (sm_103a FFMA2: PTX-only, ptxas never auto-fuses) ----
__device__ __forceinline__ u64 pack2(float lo, float hi) {
    u64 r; asm("mov.b64 %0, {%1, %2};" : "=l"(r) : "f"(lo), "f"(hi)); return r;
}
__device__ __forceinline__ void unpack2(u64 v, float& lo, float& hi) {
    asm("mov.b64 {%0, %1}, %2;" : "=f"(lo), "=f"(hi) : "l"(v));
}
__device__ __forceinline__ u64 fma2(u64 a, u64 b, u64 c) {
    u64 d; asm("fma.rn.f32x2 %0, %1, %2, %3;" : "=l"(d) : "l"(a), "l"(b), "l"(c)); return d;
}
__device__ __forceinline__ u64 mul2(u64 a, u64 b) {
    u64 d; asm("mul.rn.f32x2 %0, %1, %2;" : "=l"(d) : "l"(a), "l"(b)); return d;
}

__device__ float g_partial[NBLK];
__device__ int   g_count = 0;

__global__ void __launch_bounds__(512, 1)
ssim_main(const float* __restrict__ pred, const float* __restrict__ targ,
          float* __restrict__ out) {
    DECL_KW;
    // Raw (e,d) rows staged packed as one u64/pixel, double-buffered,
    // permanent zero x-halo pads at [0..4] and [517..521].
    __shared__ u64    sED[2][WIDTH + 12];
    __shared__ float  wsum[16];
    __shared__ double dsh[128];
    __shared__ int    sIsLast;

    const int x  = threadIdx.x;          // column 0..511
    const int y0 = blockIdx.x * TH;      // strip start output row
    const int ch = blockIdx.y;           // image-channel 0..95
    const float* __restrict__ P = pred + (size_t)ch * (WIDTH * HEIGHT);
    const float* __restrict__ T = targ + (size_t)ch * (WIDTH * HEIGHT);

    if (x < 5)          { sED[0][x] = 0ull;       sED[1][x] = 0ull; }
    if (x >= WIDTH - 5) { sED[0][x + 10] = 0ull;  sED[1][x + 10] = 0ull; }

    // packed weight pairs (KW[i], KW[i])
    u64 KW2[11];
    #pragma unroll
    for (int i = 0; i < 11; i++) KW2[i] = pack2(KW[i], KW[i]);

    // Vertical ring over 11 horizontal-conv result rows, packed:
    // rH[s] = (he,hd), rH2[s] = (he2,hd2)
    u64 rH[11], rH2[11];
    float acc = 0.f;

    // Prefetch input row k=0 (abs row y0-5).
    float pN = 0.f, tN = 0.f;
    {
        const int r = y0 - 5;
        if ((unsigned)r < (unsigned)HEIGHT) {
            pN = P[r * WIDTH + x];
            tN = T[r * WIDTH + x];
        }
    }

    // Input-row counter k = 0..TH_IN-1; ring slot = k % 11 = u (kc % 11 == 0).
    #pragma unroll 1
    for (int kc = 0; kc < TH_IN; kc += 11) {
        #pragma unroll
        for (int u = 0; u < 11; u++) {
            const int k = kc + u;
            if (k >= TH_IN) break;  // uniform across block

            const float p = pN, t = tN;
            // prefetch next input row (abs y0-4+k)
            if (k + 1 < TH_IN) {
                const int r = y0 - 4 + k;
                if ((unsigned)r < (unsigned)HEIGHT) {
                    pN = P[r * WIDTH + x];
                    tN = T[r * WIDTH + x];
                } else { pN = 0.f; tN = 0.f; }
            }

            // stage packed (e, d)
            const int buf = k & 1;
            sED[buf][x + 5] = pack2(p + t, p - t);
            __syncthreads();

            // horizontal conv, packed: (he,hd) and (he2,hd2)
            u64 hed = 0ull, hed2 = 0ull;
            #pragma unroll
            for (int i = 0; i < 11; i++) {
                const u64 v = sED[buf][x + i];
                hed  = fma2(v,          KW2[i], hed);
                hed2 = fma2(mul2(v, v), KW2[i], hed2);
            }
            rH[u] = hed; rH2[u] = hed2;

            // vertical conv + SSIM once ring is full (output row k-10)
            if (k >= 10) {
                u64 m = 0ull, c = 0ull;
                #pragma unroll
                for (int i = 0; i < 11; i++) {
                    const int s = (u + 1 + i) % 11;  // row k-10+i
                    m = fma2(rH[s],  KW2[i], m);
                    c = fma2(rH2[s], KW2[i], c);
                }
                float me, md, ce2, cd2;
                unpack2(m, me, md);
                unpack2(c, ce2, cd2);
                // mu_p*mu_t = (me^2-md^2)/4 ; mu_p^2+mu_t^2 = (me^2+md^2)/2
                // conv(pt)  = (ce2-cd2)/4   ; conv(pp)+conv(tt) = (ce2+cd2)/2
                const float A  = me * me;
                const float B  = md * md;
                const float t1 = A - B;
                const float t2 = A + B;
                const float n1 = fmaf(0.5f, t1, C1v);
                const float d1 = fmaf(0.5f, t2, C1v);
                const float n2 = fmaf(0.5f, (ce2 - cd2) - t1, C2v);
                const float d2 = fmaf(0.5f, (ce2 + cd2) - t2, C2v);
                acc += __fdividef(n1 * n2, d1 * d2);
            }
        }
    }

    // deterministic block reduction
    const int lane = x & 31;
    const int wid  = x >> 5;
    #pragma unroll
    for (int o = 16; o > 0; o >>= 1)
        acc += __shfl_down_sync(0xffffffffu, acc, o);
    if (lane == 0) wsum[wid] = acc;
    __syncthreads();
    if (wid == 0) {
        float v = (lane < 16) ? wsum[lane] : 0.f;
        #pragma unroll
        for (int o = 8; o > 0; o >>= 1)
            v += __shfl_down_sync(0xffffffffu, v, o);
        if (lane == 0)
            g_partial[blockIdx.y * STRIPS + blockIdx.x] = v;
    }

    // ---- deterministic last-block final reduction (fp64, fixed order) ----
    if (x == 0) {
        __threadfence();
        const int n = atomicAdd(&g_count, 1);
        sIsLast = (n == NBLK - 1);
    }
    __syncthreads();
    if (sIsLast) {
        __threadfence();  // acquire: see all g_partial writes
        if (x < 128) {
            double s = 0.0;
            for (int i = x; i < NBLK; i += 128)
                s += (double)g_partial[i];
            dsh[x] = s;
        }
        __syncthreads();
        #pragma unroll 1
        for (int o = 64; o > 0; o >>= 1) {
            if (x < o) dsh[x] += dsh[x + o];
            __syncthreads();
        }
        if (x == 0) {
            out[0] = (float)(1.0 - dsh[0] / 25165824.0);  // 32*3*512*512
            g_count = 0;  // reset for next graph replay
        }
    }
}

extern "C" void kernel_launch(void* const* d_in, const int* in_sizes, int n_in,
                              void* d_out, int out_size) {
    const float* pred = (const float*)d_in[0];
    const float* targ = (const float*)d_in[1];
    ssim_main<<<dim3(STRIPS, CHANNELS), 512>>>(pred, targ, (float*)d_out);
}

// round 5
// speedup vs baseline: 2.6936x; 1.3303x over previous
#include <cuda_runtime.h>

#define WIDTH    512
#define HEIGHT   512
#define TH       64
#define TH_IN    (TH + 10)            // 74 input rows per strip
#define STRIPS   (HEIGHT / TH)        // 8
#define HALVES   2
#define CHANNELS 96                   // 32 * 3
#define NBLK     (HALVES * STRIPS * CHANNELS) // 1536

#define C1v 1.0e-4f
#define C2v 9.0e-4f

typedef unsigned long long u64;

// Gaussian(sigma=1.5, k=11) weights; symmetric: KW[i] == KW[10-i].
#define DECL_KW \
    constexpr float KW[6] = { \
        0.00102838f, 0.00759876f, 0.03600078f, 0.10936081f, 0.21300554f, \
        0.26601173f }
#define KSYM(i) ((i) < 6 ? (i) : 10 - (i))

// ---- packed f32x2 helpers (PTX-only on sm_103a) ----
__device__ __forceinline__ u64 pack2(float lo, float hi) {
    u64 r; asm("mov.b64 %0, {%1, %2};" : "=l"(r) : "f"(lo), "f"(hi)); return r;
}
__device__ __forceinline__ void unpack2(u64 v, float& lo, float& hi) {
    asm("mov.b64 {%0, %1}, %2;" : "=f"(lo), "=f"(hi) : "l"(v));
}
__device__ __forceinline__ u64 fma2(u64 a, u64 b, u64 c) {
    u64 d; asm("fma.rn.f32x2 %0, %1, %2, %3;" : "=l"(d) : "l"(a), "l"(b), "l"(c)); return d;
}
__device__ __forceinline__ u64 mul2(u64 a, u64 b) {
    u64 d; asm("mul.rn.f32x2 %0, %1, %2;" : "=l"(d) : "l"(a), "l"(b)); return d;
}

__device__ float g_partial[NBLK];
__device__ int   g_count = 0;

__global__ void __launch_bounds__(256, 3)
ssim_main(const float* __restrict__ pred, const float* __restrict__ targ,
          float* __restrict__ out) {
    DECL_KW;
    // Warp-private staging: 42 packed (e,d) values per warp per row buffer
    // (32 own cols + 5 halo each side), double-buffered. No block barrier
    // in the main loop — only __syncwarp().
    __shared__ u64    sW[2][8][44];   // [buf][warp][idx], padded to 44
    __shared__ float  wsum[8];
    __shared__ double dsh[256];
    __shared__ int    sIsLast;

    const int tid  = threadIdx.x;
    const int w    = tid >> 5;
    const int l    = tid & 31;
    const int half  = blockIdx.x & 1;
    const int strip = blockIdx.x >> 1;
    const int ch    = blockIdx.y;
    const int y0    = strip * TH;
    const int colbase = half * 256 + w * 32;
    const int c0 = colbase + l;             // owned column, always in [0,512)

    // halo assignment for lanes 0..9
    int hidx = 0, chalo = 0; bool hval = false;
    if (l < 5)        { chalo = colbase - 5 + l;        hidx = l;      hval = (chalo >= 0); }
    else if (l < 10)  { chalo = colbase + 27 + l;       hidx = 32 + l; hval = (chalo < WIDTH); }

    const float* __restrict__ P = pred + (size_t)ch * (WIDTH * HEIGHT);
    const float* __restrict__ T = targ + (size_t)ch * (WIDTH * HEIGHT);

    // packed symmetric weights (6 distinct)
    u64 KW2[6];
    #pragma unroll
    for (int i = 0; i < 6; i++) KW2[i] = pack2(KW[i], KW[i]);

    // vertical ring over 11 horizontal-conv result rows (packed)
    u64 rH[11], rH2[11];
    float acc = 0.f;

    // prefetch input row k=0 (abs y0-5)
    float pN = 0.f, tN = 0.f, pHN = 0.f, tHN = 0.f;
    {
        const int r = y0 - 5;
        if ((unsigned)r < (unsigned)HEIGHT) {
            pN = P[r * WIDTH + c0];
            tN = T[r * WIDTH + c0];
            if (hval) { pHN = P[r * WIDTH + chalo]; tHN = T[r * WIDTH + chalo]; }
        }
    }

    // k = 0..TH_IN-1; ring slot = k % 11 (kc % 11 == 0 keeps it compile-time)
    #pragma unroll 1
    for (int kc = 0; kc < TH_IN; kc += 11) {
        #pragma unroll
        for (int u = 0; u < 11; u++) {
            const int k = kc + u;
            if (k >= TH_IN) break;   // uniform

            const float p = pN, t = tN, ph = pHN, th = tHN;
            if (k + 1 < TH_IN) {     // prefetch abs row y0-4+k
                const int r = y0 - 4 + k;
                if ((unsigned)r < (unsigned)HEIGHT) {
                    pN = P[r * WIDTH + c0];
                    tN = T[r * WIDTH + c0];
                    if (hval) { pHN = P[r * WIDTH + chalo]; tHN = T[r * WIDTH + chalo]; }
                    else      { pHN = 0.f; tHN = 0.f; }
                } else { pN = 0.f; tN = 0.f; pHN = 0.f; tHN = 0.f; }
            }

            // stage packed (e,d); warp-private, so only syncwarp needed
            const int buf = k & 1;
            sW[buf][w][5 + l] = pack2(p + t, p - t);
            if (l < 10) sW[buf][w][hidx] = pack2(ph + th, ph - th);
            __syncwarp();

            // horizontal conv (11 LDS.64 + 11 MUL2 + 22 FMA2)
            u64 hed = 0ull, hed2 = 0ull;
            #pragma unroll
            for (int i = 0; i < 11; i++) {
                const u64 v = sW[buf][w][l + i];
                hed  = fma2(v,          KW2[KSYM(i)], hed);
                hed2 = fma2(mul2(v, v), KW2[KSYM(i)], hed2);
            }
            rH[u] = hed; rH2[u] = hed2;

            // vertical conv + SSIM once ring full (output row k-10)
            if (k >= 10) {
                u64 m = 0ull, c = 0ull;
                #pragma unroll
                for (int i = 0; i < 11; i++) {
                    const int s = (u + 1 + i) % 11;
                    m = fma2(rH[s],  KW2[KSYM(i)], m);
                    c = fma2(rH2[s], KW2[KSYM(i)], c);
                }
                float me, md, ce2, cd2;
                unpack2(m, me, md);
                unpack2(c, ce2, cd2);
                const float A  = me * me;
                const float B  = md * md;
                const float t1 = A - B;
                const float t2 = A + B;
                const float n1 = fmaf(0.5f, t1, C1v);
                const float d1 = fmaf(0.5f, t2, C1v);
                const float n2 = fmaf(0.5f, (ce2 - cd2) - t1, C2v);
                const float d2 = fmaf(0.5f, (ce2 + cd2) - t2, C2v);
                acc += __fdividef(n1 * n2, d1 * d2);
            }
        }
    }

    // deterministic block reduction (one barrier, at the very end)
    #pragma unroll
    for (int o = 16; o > 0; o >>= 1)
        acc += __shfl_down_sync(0xffffffffu, acc, o);
    if (l == 0) wsum[w] = acc;
    __syncthreads();
    if (tid < 32) {
        float v = (l < 8) ? wsum[l] : 0.f;
        #pragma unroll
        for (int o = 4; o > 0; o >>= 1)
            v += __shfl_down_sync(0xffffffffu, v, o);
        if (l == 0)
            g_partial[blockIdx.y * (HALVES * STRIPS) + blockIdx.x] = v;
    }

    // deterministic last-block final reduction (fp64, fixed order)
    if (tid == 0) {
        __threadfence();
        const int n = atomicAdd(&g_count, 1);
        sIsLast = (n == NBLK - 1);
    }
    __syncthreads();
    if (sIsLast) {
        __threadfence();
        double s = 0.0;
        for (int i = tid; i < NBLK; i += 256)
            s += (double)g_partial[i];
        dsh[tid] = s;
        __syncthreads();
        #pragma unroll 1
        for (int o = 128; o > 0; o >>= 1) {
            if (tid < o) dsh[tid] += dsh[tid + o];
            __syncthreads();
        }
        if (tid == 0) {
            out[0] = (float)(1.0 - dsh[0] / 25165824.0);  // 32*3*512*512
            g_count = 0;  // reset for next graph replay
        }
    }
}

extern "C" void kernel_launch(void* const* d_in, const int* in_sizes, int n_in,
                              void* d_out, int out_size) {
    const float* pred = (const float*)d_in[0];
    const float* targ = (const float*)d_in[1];
    ssim_main<<<dim3(HALVES * STRIPS, CHANNELS), 256>>>(pred, targ, (float*)d_out);
}